// round 14
// baseline (speedup 1.0000x reference)
#include <cuda_runtime.h>
#include <cuda_bf16.h>
#include <cuda_fp16.h>
#include <math.h>
#include <stdint.h>

#define N_NODES_C 100000
#define N_EDGES_C 600000
#define D_C       128
#define TPB       256
#define TILE_M    128
#define GEMM_GRID ((N_NODES_C + TILE_M - 1) / TILE_M)   // 782

#define RS        136                      // smem row stride in fp16 (conflict-free ldmatrix)
#define TILE_HALF (TILE_M * RS)
#define TILE_BYTES_SM (TILE_HALF * 2)      // 34816 B

#define CAP       64                       // slots per node (Poisson(6): P(deg>=64) ~ 1e-40)

// -------- device scratch (static; zero-initialized at load) --------
__device__ int g_cnt[N_NODES_C];                        // zero between launches (self-restoring)
__device__ int g_bucket[(size_t)N_NODES_C * CAP];       // 25.6 MB
__device__ __half g_Yh[(size_t)N_NODES_C * D_C];        // Y = feat @ W^T in fp16 (25.6 MB)

__device__ __forceinline__ uint32_t smem_u32(const void* p) {
    uint32_t a;
    asm("{ .reg .u64 t; cvta.to.shared.u64 t, %1; cvt.u32.u64 %0, t; }" : "=r"(a) : "l"(p));
    return a;
}

// ---------------------------------------------------------------------------
// K1: fused  [edge bucket-scatter] + [GEMM Y = feat @ W^T -> fp16]
// ---------------------------------------------------------------------------
__device__ __forceinline__ void ldsm_x4(uint32_t addr, uint32_t& r0, uint32_t& r1,
                                        uint32_t& r2, uint32_t& r3) {
    asm volatile("ldmatrix.sync.aligned.m8n8.x4.shared.b16 {%0,%1,%2,%3}, [%4];"
                 : "=r"(r0), "=r"(r1), "=r"(r2), "=r"(r3) : "r"(addr));
}
__device__ __forceinline__ void mma16816h(float& c0, float& c1, float& c2, float& c3,
                                          uint32_t a0, uint32_t a1, uint32_t a2, uint32_t a3,
                                          uint32_t b0, uint32_t b1) {
    asm volatile("mma.sync.aligned.m16n8k16.row.col.f32.f16.f16.f32 "
                 "{%0,%1,%2,%3}, {%4,%5,%6,%7}, {%8,%9}, {%0,%1,%2,%3};"
                 : "+f"(c0), "+f"(c1), "+f"(c2), "+f"(c3)
                 : "r"(a0), "r"(a1), "r"(a2), "r"(a3), "r"(b0), "r"(b1));
}

__global__ __launch_bounds__(TPB, 2) void gemm_scatter_kernel(const float* __restrict__ feat,
                                                              const float* __restrict__ W,
                                                              const int* __restrict__ src,
                                                              const int* __restrict__ dst,
                                                              int n_edges) {
    extern __shared__ __align__(16) __half sm[];
    __half* Ah = sm;
    __half* Bh = Ah + TILE_HALF;

    const int tid  = threadIdx.x;
    const int wid  = tid >> 5;
    const int lane = tid & 31;
    const int base = blockIdx.x * TILE_M;

    // ---- edge scatter, grid-strided (~3 edges/thread); latency hides under fill ----
    {
        const int stride = GEMM_GRID * TPB;
        for (int e = blockIdx.x * TPB + tid; e < n_edges; e += stride) {
            int d   = dst[e];
            int s   = src[e];
            int pos = atomicAdd(&g_cnt[d], 1);
            if (pos < CAP) g_bucket[(size_t)d * CAP + pos] = s;
        }
    }

    // ---- tile fill: feat -> fp16 A, W -> fp16 B ----
    #pragma unroll
    for (int it = 0; it < 8; ++it) {
        int idx = tid + it * TPB;
        int row = idx >> 4;
        int kc  = (idx & 15) << 3;
        int so  = row * RS + kc;
        int node = base + row;

        {
            uint32_t h[4];
            if (node < N_NODES_C) {
                const float4* fp = (const float4*)(feat + (size_t)node * D_C + kc);
                float4 f0 = fp[0], f1 = fp[1];
                __half2 p0 = __floats2half2_rn(f0.x, f0.y);
                __half2 p1 = __floats2half2_rn(f0.z, f0.w);
                __half2 p2 = __floats2half2_rn(f1.x, f1.y);
                __half2 p3 = __floats2half2_rn(f1.z, f1.w);
                h[0] = *(uint32_t*)&p0; h[1] = *(uint32_t*)&p1;
                h[2] = *(uint32_t*)&p2; h[3] = *(uint32_t*)&p3;
            } else {
                h[0] = h[1] = h[2] = h[3] = 0u;
            }
            *(uint4*)(Ah + so) = make_uint4(h[0], h[1], h[2], h[3]);
        }
        {
            const float4* wp = (const float4*)(W + (size_t)row * D_C + kc);
            float4 w0 = wp[0], w1 = wp[1];
            __half2 p0 = __floats2half2_rn(w0.x, w0.y);
            __half2 p1 = __floats2half2_rn(w0.z, w0.w);
            __half2 p2 = __floats2half2_rn(w1.x, w1.y);
            __half2 p3 = __floats2half2_rn(w1.z, w1.w);
            *(uint4*)(Bh + so) = make_uint4(*(uint32_t*)&p0, *(uint32_t*)&p1,
                                            *(uint32_t*)&p2, *(uint32_t*)&p3);
        }
    }
    __syncthreads();

    const int m0 = (wid & 3) * 32;
    const int n0 = (wid >> 2) * 64;

    float acc[2][8][4];
    #pragma unroll
    for (int f = 0; f < 2; f++)
        #pragma unroll
        for (int nb = 0; nb < 8; nb++)
            #pragma unroll
            for (int j = 0; j < 4; j++) acc[f][nb][j] = 0.f;

    uint32_t aBase[2];
    #pragma unroll
    for (int f = 0; f < 2; f++)
        aBase[f] = smem_u32(Ah) +
                   (uint32_t)(((m0 + f * 16 + (lane & 15)) * RS + ((lane >> 4) << 3)) * 2);
    uint32_t bBase[4];
    #pragma unroll
    for (int p = 0; p < 4; p++)
        bBase[p] = smem_u32(Bh) +
                   (uint32_t)(((n0 + 16 * p + (lane & 7) + ((lane >> 4) << 3)) * RS +
                               (((lane >> 3) & 1) << 3)) * 2);

    #pragma unroll
    for (int kk = 0; kk < 8; kk++) {
        uint32_t koff = (uint32_t)(kk * 16 * 2);
        uint32_t a[2][4];
        #pragma unroll
        for (int f = 0; f < 2; f++)
            ldsm_x4(aBase[f] + koff, a[f][0], a[f][1], a[f][2], a[f][3]);
        #pragma unroll
        for (int p = 0; p < 4; p++) {
            uint32_t b0, b1, b2, b3;
            ldsm_x4(bBase[p] + koff, b0, b1, b2, b3);
            #pragma unroll
            for (int f = 0; f < 2; f++) {
                mma16816h(acc[f][2*p  ][0], acc[f][2*p  ][1], acc[f][2*p  ][2], acc[f][2*p  ][3],
                          a[f][0], a[f][1], a[f][2], a[f][3], b0, b1);
                mma16816h(acc[f][2*p+1][0], acc[f][2*p+1][1], acc[f][2*p+1][2], acc[f][2*p+1][3],
                          a[f][0], a[f][1], a[f][2], a[f][3], b2, b3);
            }
        }
    }

    const int qr = lane >> 2;
    const int qc = (lane & 3) * 2;
    #pragma unroll
    for (int f = 0; f < 2; f++) {
        int m_lo = m0 + f * 16 + qr;
        int m_hi = m_lo + 8;
        int node_lo = base + m_lo;
        int node_hi = base + m_hi;
        #pragma unroll
        for (int nb = 0; nb < 8; nb++) {
            int col = n0 + nb * 8 + qc;
            if (node_lo < N_NODES_C)
                *(__half2*)(g_Yh + (size_t)node_lo * D_C + col) =
                    __floats2half2_rn(acc[f][nb][0], acc[f][nb][1]);
            if (node_hi < N_NODES_C)
                *(__half2*)(g_Yh + (size_t)node_hi * D_C + col) =
                    __floats2half2_rn(acc[f][nb][2], acc[f][nb][3]);
        }
    }
}

// ---------------------------------------------------------------------------
// K2: final aggregate on fp16 Y:  out = (sum Y[src] + Y[self]) * norm + b
// ---------------------------------------------------------------------------
__device__ __forceinline__ void acc_row(float4& a, uint2 r) {
    float2 p0 = __half22float2(*(__half2*)&r.x);
    float2 p1 = __half22float2(*(__half2*)&r.y);
    a.x += p0.x; a.y += p0.y; a.z += p1.x; a.w += p1.y;
}

__global__ __launch_bounds__(TPB) void aggregate_kernel(const float* __restrict__ bias,
                                                        float* __restrict__ out) {
    int node = (blockIdx.x * blockDim.x + threadIdx.x) >> 5;
    int lane = threadIdx.x & 31;
    if (node >= N_NODES_C) return;

    int cnt = 0;
    if (lane == 0) cnt = atomicExch(&g_cnt[node], 0);   // read deg + restore to 0
    cnt = __shfl_sync(0xffffffffu, cnt, 0);
    int deg = cnt < CAP ? cnt : CAP;

    float4 a0 = make_float4(0.f, 0.f, 0.f, 0.f);
    acc_row(a0, ((const uint2*)(g_Yh + (size_t)node * D_C))[lane]);   // self

    const int* bkt = g_bucket + (size_t)node * CAP;

    float4 a1 = make_float4(0.f, 0.f, 0.f, 0.f);
    float4 a2 = make_float4(0.f, 0.f, 0.f, 0.f);
    float4 a3 = make_float4(0.f, 0.f, 0.f, 0.f);
    int e = 0;
    for (; e + 4 <= deg; e += 4) {
        int s0 = __ldg(bkt + e + 0);
        int s1 = __ldg(bkt + e + 1);
        int s2 = __ldg(bkt + e + 2);
        int s3 = __ldg(bkt + e + 3);
        uint2 r0 = ((const uint2*)(g_Yh + (size_t)s0 * D_C))[lane];
        uint2 r1 = ((const uint2*)(g_Yh + (size_t)s1 * D_C))[lane];
        uint2 r2 = ((const uint2*)(g_Yh + (size_t)s2 * D_C))[lane];
        uint2 r3 = ((const uint2*)(g_Yh + (size_t)s3 * D_C))[lane];
        acc_row(a0, r0);
        acc_row(a1, r1);
        acc_row(a2, r2);
        acc_row(a3, r3);
    }
    for (; e < deg; ++e) {
        int s0 = __ldg(bkt + e);
        acc_row(a0, ((const uint2*)(g_Yh + (size_t)s0 * D_C))[lane]);
    }
    a0.x += a1.x + a2.x + a3.x;
    a0.y += a1.y + a2.y + a3.y;
    a0.z += a1.z + a2.z + a3.z;
    a0.w += a1.w + a2.w + a3.w;

    float nrm = rsqrtf(fmaxf((float)cnt, 1.0f));
    float4 bv = __ldg((const float4*)(bias) + lane);
    float4 o;
    o.x = a0.x * nrm + bv.x;
    o.y = a0.y * nrm + bv.y;
    o.z = a0.z * nrm + bv.z;
    o.w = a0.w * nrm + bv.w;
    ((float4*)(out + (size_t)node * D_C))[lane] = o;
}

// ---------------------------------------------------------------------------
// kernel_launch — 2 kernels, single stream
// ---------------------------------------------------------------------------
extern "C" void kernel_launch(void* const* d_in, const int* in_sizes, int n_in,
                              void* d_out, int out_size) {
    const float* feat = (const float*)d_in[0];   // [100000,128] f32
    const int*   src  = (const int*)d_in[1];     // [600000] i32
    const int*   dst  = (const int*)d_in[2];     // [600000] i32
    const float* W    = (const float*)d_in[3];   // [128,128] f32
    const float* b    = (const float*)d_in[4];   // [128] f32
    float*       out  = (float*)d_out;

    const int n_edges = in_sizes[1];

    static bool smem_set = []() {
        cudaFuncSetAttribute(gemm_scatter_kernel,
                             cudaFuncAttributeMaxDynamicSharedMemorySize,
                             2 * TILE_BYTES_SM);
        return true;
    }();
    (void)smem_set;

    const int smem_bytes = 2 * TILE_BYTES_SM;    // 69632 B

    // 1) fused scatter + GEMM
    gemm_scatter_kernel<<<GEMM_GRID, TPB, smem_bytes>>>(feat, W, src, dst, n_edges);

    // 2) out = (sum Y[src] + Y[self]) * norm + b
    aggregate_kernel<<<(N_NODES_C * 32 + TPB - 1) / TPB, TPB>>>(b, out);
}

// round 15
// speedup vs baseline: 1.0728x; 1.0728x over previous
#include <cuda_runtime.h>
#include <cuda_bf16.h>
#include <cuda_fp16.h>
#include <math.h>
#include <stdint.h>

#define N_NODES_C 100000
#define N_EDGES_C 600000
#define D_C       128
#define TPB       256
#define TILE_M    128
#define GEMM_GRID ((N_NODES_C + TILE_M - 1) / TILE_M)   // 782

#define RS        136                      // smem row stride in fp16 (conflict-free ldmatrix)
#define TILE_HALF (TILE_M * RS)
#define TILE_BYTES_SM (TILE_HALF * 2)      // 34816 B

#define CAP       64                       // slots per node (Poisson(6): P(deg>=64) ~ 1e-40)

// -------- device scratch (static; zero-initialized at load) --------
__device__ int g_cnt[N_NODES_C];                        // zero between launches (self-restoring)
__device__ int g_bucket[(size_t)N_NODES_C * CAP];       // 25.6 MB
__device__ __half g_Yh[(size_t)N_NODES_C * D_C];        // Y = feat @ W^T in fp16 (25.6 MB)

__device__ __forceinline__ uint32_t smem_u32(const void* p) {
    uint32_t a;
    asm("{ .reg .u64 t; cvta.to.shared.u64 t, %1; cvt.u32.u64 %0, t; }" : "=r"(a) : "l"(p));
    return a;
}

// ---------------------------------------------------------------------------
// K1: GEMM  Y = feat @ W^T  (single-product fp16 HMMA) -> fp16 Y
// ---------------------------------------------------------------------------
__device__ __forceinline__ void ldsm_x4(uint32_t addr, uint32_t& r0, uint32_t& r1,
                                        uint32_t& r2, uint32_t& r3) {
    asm volatile("ldmatrix.sync.aligned.m8n8.x4.shared.b16 {%0,%1,%2,%3}, [%4];"
                 : "=r"(r0), "=r"(r1), "=r"(r2), "=r"(r3) : "r"(addr));
}
__device__ __forceinline__ void mma16816h(float& c0, float& c1, float& c2, float& c3,
                                          uint32_t a0, uint32_t a1, uint32_t a2, uint32_t a3,
                                          uint32_t b0, uint32_t b1) {
    asm volatile("mma.sync.aligned.m16n8k16.row.col.f32.f16.f16.f32 "
                 "{%0,%1,%2,%3}, {%4,%5,%6,%7}, {%8,%9}, {%0,%1,%2,%3};"
                 : "+f"(c0), "+f"(c1), "+f"(c2), "+f"(c3)
                 : "r"(a0), "r"(a1), "r"(a2), "r"(a3), "r"(b0), "r"(b1));
}

__global__ __launch_bounds__(TPB, 2) void gemm_kernel(const float* __restrict__ feat,
                                                      const float* __restrict__ W) {
    extern __shared__ __align__(16) __half sm[];
    __half* Ah = sm;
    __half* Bh = Ah + TILE_HALF;

    const int tid  = threadIdx.x;
    const int wid  = tid >> 5;
    const int lane = tid & 31;
    const int base = blockIdx.x * TILE_M;

    #pragma unroll
    for (int it = 0; it < 8; ++it) {
        int idx = tid + it * TPB;
        int row = idx >> 4;
        int kc  = (idx & 15) << 3;
        int so  = row * RS + kc;
        int node = base + row;

        {
            uint32_t h[4];
            if (node < N_NODES_C) {
                const float4* fp = (const float4*)(feat + (size_t)node * D_C + kc);
                float4 f0 = fp[0], f1 = fp[1];
                __half2 p0 = __floats2half2_rn(f0.x, f0.y);
                __half2 p1 = __floats2half2_rn(f0.z, f0.w);
                __half2 p2 = __floats2half2_rn(f1.x, f1.y);
                __half2 p3 = __floats2half2_rn(f1.z, f1.w);
                h[0] = *(uint32_t*)&p0; h[1] = *(uint32_t*)&p1;
                h[2] = *(uint32_t*)&p2; h[3] = *(uint32_t*)&p3;
            } else {
                h[0] = h[1] = h[2] = h[3] = 0u;
            }
            *(uint4*)(Ah + so) = make_uint4(h[0], h[1], h[2], h[3]);
        }
        {
            const float4* wp = (const float4*)(W + (size_t)row * D_C + kc);
            float4 w0 = wp[0], w1 = wp[1];
            __half2 p0 = __floats2half2_rn(w0.x, w0.y);
            __half2 p1 = __floats2half2_rn(w0.z, w0.w);
            __half2 p2 = __floats2half2_rn(w1.x, w1.y);
            __half2 p3 = __floats2half2_rn(w1.z, w1.w);
            *(uint4*)(Bh + so) = make_uint4(*(uint32_t*)&p0, *(uint32_t*)&p1,
                                            *(uint32_t*)&p2, *(uint32_t*)&p3);
        }
    }
    __syncthreads();

    const int m0 = (wid & 3) * 32;
    const int n0 = (wid >> 2) * 64;

    float acc[2][8][4];
    #pragma unroll
    for (int f = 0; f < 2; f++)
        #pragma unroll
        for (int nb = 0; nb < 8; nb++)
            #pragma unroll
            for (int j = 0; j < 4; j++) acc[f][nb][j] = 0.f;

    uint32_t aBase[2];
    #pragma unroll
    for (int f = 0; f < 2; f++)
        aBase[f] = smem_u32(Ah) +
                   (uint32_t)(((m0 + f * 16 + (lane & 15)) * RS + ((lane >> 4) << 3)) * 2);
    uint32_t bBase[4];
    #pragma unroll
    for (int p = 0; p < 4; p++)
        bBase[p] = smem_u32(Bh) +
                   (uint32_t)(((n0 + 16 * p + (lane & 7) + ((lane >> 4) << 3)) * RS +
                               (((lane >> 3) & 1) << 3)) * 2);

    #pragma unroll
    for (int kk = 0; kk < 8; kk++) {
        uint32_t koff = (uint32_t)(kk * 16 * 2);
        uint32_t a[2][4];
        #pragma unroll
        for (int f = 0; f < 2; f++)
            ldsm_x4(aBase[f] + koff, a[f][0], a[f][1], a[f][2], a[f][3]);
        #pragma unroll
        for (int p = 0; p < 4; p++) {
            uint32_t b0, b1, b2, b3;
            ldsm_x4(bBase[p] + koff, b0, b1, b2, b3);
            #pragma unroll
            for (int f = 0; f < 2; f++) {
                mma16816h(acc[f][2*p  ][0], acc[f][2*p  ][1], acc[f][2*p  ][2], acc[f][2*p  ][3],
                          a[f][0], a[f][1], a[f][2], a[f][3], b0, b1);
                mma16816h(acc[f][2*p+1][0], acc[f][2*p+1][1], acc[f][2*p+1][2], acc[f][2*p+1][3],
                          a[f][0], a[f][1], a[f][2], a[f][3], b2, b3);
            }
        }
    }

    const int qr = lane >> 2;
    const int qc = (lane & 3) * 2;
    #pragma unroll
    for (int f = 0; f < 2; f++) {
        int m_lo = m0 + f * 16 + qr;
        int m_hi = m_lo + 8;
        int node_lo = base + m_lo;
        int node_hi = base + m_hi;
        #pragma unroll
        for (int nb = 0; nb < 8; nb++) {
            int col = n0 + nb * 8 + qc;
            if (node_lo < N_NODES_C)
                *(__half2*)(g_Yh + (size_t)node_lo * D_C + col) =
                    __floats2half2_rn(acc[f][nb][0], acc[f][nb][1]);
            if (node_hi < N_NODES_C)
                *(__half2*)(g_Yh + (size_t)node_hi * D_C + col) =
                    __floats2half2_rn(acc[f][nb][2], acc[f][nb][3]);
        }
    }
}

// ---------------------------------------------------------------------------
// K2: bucket scatter
// ---------------------------------------------------------------------------
__global__ void scatter_kernel(const int* __restrict__ src,
                               const int* __restrict__ dst, int n_edges) {
    int e = blockIdx.x * blockDim.x + threadIdx.x;
    if (e < n_edges) {
        int d   = dst[e];
        int pos = atomicAdd(&g_cnt[d], 1);
        if (pos < CAP) g_bucket[(size_t)d * CAP + pos] = src[e];
    }
}

// ---------------------------------------------------------------------------
// K3: final aggregate — dependency-chain-minimized.
//     All independent loads (cnt, bucket slots, self row) issue up front;
//     neighbor indices come from registers via shfl, so all row loads can
//     stream back-to-back.
// ---------------------------------------------------------------------------
__device__ __forceinline__ void acc_row(float4& a, uint2 r) {
    float2 p0 = __half22float2(*(__half2*)&r.x);
    float2 p1 = __half22float2(*(__half2*)&r.y);
    a.x += p0.x; a.y += p0.y; a.z += p1.x; a.w += p1.y;
}
__device__ __forceinline__ const uint2* yrow(int s) {
    return (const uint2*)(g_Yh + ((uint32_t)s << 7));
}

__global__ __launch_bounds__(TPB) void aggregate_kernel(const float* __restrict__ bias,
                                                        float* __restrict__ out) {
    int node = (blockIdx.x * blockDim.x + threadIdx.x) >> 5;
    int lane = threadIdx.x & 31;
    if (node >= N_NODES_C) return;

    // --- issue all independent loads first ---
    int cnt = 0;
    if (lane == 0) cnt = atomicExch(&g_cnt[node], 0);           // deg + reset
    int slot = __ldg(g_bucket + (size_t)node * CAP + lane);      // slots 0..31
    uint2 selfr = yrow(node)[lane];                              // self row

    cnt = __shfl_sync(0xffffffffu, cnt, 0);
    int deg = cnt < CAP ? cnt : CAP;

    float4 a0 = make_float4(0.f, 0.f, 0.f, 0.f);
    float4 a1 = make_float4(0.f, 0.f, 0.f, 0.f);
    float4 a2 = make_float4(0.f, 0.f, 0.f, 0.f);
    float4 a3 = make_float4(0.f, 0.f, 0.f, 0.f);
    acc_row(a0, selfr);

    int d32 = deg < 32 ? deg : 32;
    int e = 0;
    for (; e + 4 <= d32; e += 4) {
        int s0 = __shfl_sync(0xffffffffu, slot, e + 0);
        int s1 = __shfl_sync(0xffffffffu, slot, e + 1);
        int s2 = __shfl_sync(0xffffffffu, slot, e + 2);
        int s3 = __shfl_sync(0xffffffffu, slot, e + 3);
        uint2 r0 = yrow(s0)[lane];
        uint2 r1 = yrow(s1)[lane];
        uint2 r2 = yrow(s2)[lane];
        uint2 r3 = yrow(s3)[lane];
        acc_row(a0, r0);
        acc_row(a1, r1);
        acc_row(a2, r2);
        acc_row(a3, r3);
    }
    for (; e < d32; ++e) {
        int s0 = __shfl_sync(0xffffffffu, slot, e);
        acc_row(a0, yrow(s0)[lane]);
    }
    // rare tail: slots 32..deg-1 (P ~ 1e-15 per node)
    for (; e < deg; ++e) {
        int s0 = __ldg(g_bucket + (size_t)node * CAP + e);
        acc_row(a0, yrow(s0)[lane]);
    }

    a0.x += a1.x + a2.x + a3.x;
    a0.y += a1.y + a2.y + a3.y;
    a0.z += a1.z + a2.z + a3.z;
    a0.w += a1.w + a2.w + a3.w;

    float nrm = rsqrtf(fmaxf((float)cnt, 1.0f));
    float4 bv = __ldg((const float4*)(bias) + lane);
    float4 o;
    o.x = a0.x * nrm + bv.x;
    o.y = a0.y * nrm + bv.y;
    o.z = a0.z * nrm + bv.z;
    o.w = a0.w * nrm + bv.w;
    ((float4*)(out + ((uint32_t)node << 7)))[lane] = o;
}

// ---------------------------------------------------------------------------
// kernel_launch — GEMM overlapped with bucket scatter via fork/join
// ---------------------------------------------------------------------------
extern "C" void kernel_launch(void* const* d_in, const int* in_sizes, int n_in,
                              void* d_out, int out_size) {
    const float* feat = (const float*)d_in[0];   // [100000,128] f32
    const int*   src  = (const int*)d_in[1];     // [600000] i32
    const int*   dst  = (const int*)d_in[2];     // [600000] i32
    const float* W    = (const float*)d_in[3];   // [128,128] f32
    const float* b    = (const float*)d_in[4];   // [128] f32
    float*       out  = (float*)d_out;

    const int n_edges = in_sizes[1];

    static cudaStream_t s_side = []() {
        cudaStream_t s; cudaStreamCreateWithFlags(&s, cudaStreamNonBlocking); return s;
    }();
    static cudaEvent_t ev_fork = []() {
        cudaEvent_t e; cudaEventCreateWithFlags(&e, cudaEventDisableTiming); return e;
    }();
    static cudaEvent_t ev_join = []() {
        cudaEvent_t e; cudaEventCreateWithFlags(&e, cudaEventDisableTiming); return e;
    }();
    static bool smem_set = []() {
        cudaFuncSetAttribute(gemm_kernel,
                             cudaFuncAttributeMaxDynamicSharedMemorySize,
                             2 * TILE_BYTES_SM);
        return true;
    }();
    (void)smem_set;

    const int smem_bytes = 2 * TILE_BYTES_SM;    // 69632 B

    // Fork
    cudaEventRecord(ev_fork, 0);
    cudaStreamWaitEvent(s_side, ev_fork, 0);

    // Branch A (main): Y = feat @ W^T (fp16)
    gemm_kernel<<<GEMM_GRID, TPB, smem_bytes>>>(feat, W);

    // Branch B (side): bucket scatter
    scatter_kernel<<<(n_edges + TPB - 1) / TPB, TPB, 0, s_side>>>(src, dst, n_edges);

    // Join
    cudaEventRecord(ev_join, s_side);
    cudaStreamWaitEvent(0, ev_join, 0);

    // out = (sum Y[src] + Y[self]) * norm + b
    aggregate_kernel<<<(N_NODES_C * 32 + TPB - 1) / TPB, TPB>>>(b, out);
}